// round 1
// baseline (speedup 1.0000x reference)
#include <cuda_runtime.h>
#include <math.h>

// ---------------------------------------------------------------------------
// Problem constants: B=2, T=2048, D=1024, NH=16, DH=64, MLP=4096
// M = B*T = 4096 rows everywhere.
// ---------------------------------------------------------------------------

#define M_ROWS 4096
#define D_DIM  1024
#define D3     3072
#define MLP_D  4096

// Scratch buffers (device globals: no allocation allowed in kernel_launch)
__device__ float g_xn  [M_ROWS * D_DIM];   // LN1 output
__device__ float g_qkv [M_ROWS * D3];      // qkv projection
__device__ float g_att [M_ROWS * D_DIM];   // attention output (heads merged)
__device__ float g_x   [M_ROWS * D_DIM];   // residual-1 output
__device__ float g_hn  [M_ROWS * D_DIM];   // LN2 output
__device__ float g_h   [M_ROWS * MLP_D];   // gelu(h@w1+b1)

// ---------------------------------------------------------------------------
// LayerNorm: one block (256 threads) per row of 1024 floats.
// ---------------------------------------------------------------------------
__global__ void ln_k(const float* __restrict__ x, const float* __restrict__ g,
                     const float* __restrict__ b, float* __restrict__ y) {
    __shared__ float rs[8], rss[8], sh[2];
    const int row = blockIdx.x;
    const int tid = threadIdx.x;
    const float4 v = *(const float4*)(x + (size_t)row * 1024 + tid * 4);
    float s  = v.x + v.y + v.z + v.w;
    float ss = v.x * v.x + v.y * v.y + v.z * v.z + v.w * v.w;
#pragma unroll
    for (int off = 16; off >= 1; off >>= 1) {
        s  += __shfl_xor_sync(0xffffffffu, s, off);
        ss += __shfl_xor_sync(0xffffffffu, ss, off);
    }
    if ((tid & 31) == 0) { rs[tid >> 5] = s; rss[tid >> 5] = ss; }
    __syncthreads();
    if (tid == 0) {
        float S = 0.f, SS = 0.f;
#pragma unroll
        for (int w = 0; w < 8; w++) { S += rs[w]; SS += rss[w]; }
        sh[0] = S * (1.0f / 1024.0f);
        sh[1] = SS * (1.0f / 1024.0f);
    }
    __syncthreads();
    const float mu   = sh[0];
    const float var  = sh[1] - mu * mu;
    const float rstd = rsqrtf(var + 1e-5f);
    const float4 gg = *(const float4*)(g + tid * 4);
    const float4 bb = *(const float4*)(b + tid * 4);
    float4 o;
    o.x = (v.x - mu) * rstd * gg.x + bb.x;
    o.y = (v.y - mu) * rstd * gg.y + bb.y;
    o.z = (v.z - mu) * rstd * gg.z + bb.z;
    o.w = (v.w - mu) * rstd * gg.w + bb.w;
    *(float4*)(y + (size_t)row * 1024 + tid * 4) = o;
}

// ---------------------------------------------------------------------------
// SGEMM: C[M,N] = A[M,K] @ B[K,N] (+ epilogue)
//   EPI 0: none     1: +bias[n]     2: +bias[n]+res[m,n]     3: gelu(.+bias)
// 128x128 tile, BK=8, 256 threads, 8x8 per-thread microtile.
// Requires M%128==0, N%128==0, K%8==0 (true for all calls here).
// ---------------------------------------------------------------------------
#define BM 128
#define BN 128
#define BK 8
#define TM 8
#define TN 8

template <int EPI>
__global__ __launch_bounds__(256, 2)
void sgemm_k(const float* __restrict__ A, const float* __restrict__ Bm,
             const float* __restrict__ bias, const float* __restrict__ res,
             float* __restrict__ C, int M, int N, int K) {
    __shared__ float As[BK][BM];
    __shared__ float Bs[BK][BN];

    const int tid = threadIdx.x;
    const int m0 = blockIdx.y * BM;
    const int n0 = blockIdx.x * BN;
    const int tx = tid & 15;
    const int ty = tid >> 4;

    const int arow = tid >> 1;          // 0..127
    const int acol = (tid & 1) * 4;     // 0 or 4
    const int brow = tid >> 5;          // 0..7
    const int bcol = (tid & 31) * 4;    // 0..124

    const float* Aptr = A + (size_t)(m0 + arow) * K + acol;
    const float* Bptr = Bm + (size_t)brow * N + n0 + bcol;

    float acc[TM][TN];
#pragma unroll
    for (int i = 0; i < TM; i++)
#pragma unroll
        for (int j = 0; j < TN; j++) acc[i][j] = 0.f;

    for (int k0 = 0; k0 < K; k0 += BK) {
        const float4 a4 = *(const float4*)(Aptr);
        const float4 b4 = *(const float4*)(Bptr);
        As[acol + 0][arow] = a4.x;
        As[acol + 1][arow] = a4.y;
        As[acol + 2][arow] = a4.z;
        As[acol + 3][arow] = a4.w;
        *(float4*)&Bs[brow][bcol] = b4;
        __syncthreads();

#pragma unroll
        for (int k = 0; k < BK; k++) {
            float a[TM], bb[TN];
            *(float4*)&a[0]  = *(const float4*)&As[k][ty * TM];
            *(float4*)&a[4]  = *(const float4*)&As[k][ty * TM + 4];
            *(float4*)&bb[0] = *(const float4*)&Bs[k][tx * TN];
            *(float4*)&bb[4] = *(const float4*)&Bs[k][tx * TN + 4];
#pragma unroll
            for (int i = 0; i < TM; i++)
#pragma unroll
                for (int j = 0; j < TN; j++)
                    acc[i][j] += a[i] * bb[j];
        }
        __syncthreads();
        Aptr += BK;
        Bptr += (size_t)BK * N;
    }

    // Epilogue
#pragma unroll
    for (int i = 0; i < TM; i++) {
        const int m = m0 + ty * TM + i;
#pragma unroll
        for (int j = 0; j < TN; j += 4) {
            const int n = n0 + tx * TN + j;
            float vv[4];
#pragma unroll
            for (int u = 0; u < 4; u++) {
                float v = acc[i][j + u];
                if (EPI >= 1) v += bias[n + u];
                if (EPI == 2) v += res[(size_t)m * N + n + u];
                if (EPI == 3) v = 0.5f * v * (1.0f + erff(v * 0.7071067811865476f));
                vv[u] = v;
            }
            *(float4*)&C[(size_t)m * N + n] = make_float4(vv[0], vv[1], vv[2], vv[3]);
        }
    }
}

// ---------------------------------------------------------------------------
// Flash attention (fp32, no mask): block = (qtile=64 rows, head h, batch b).
// 256 threads, 4x4 microtile, online softmax. DH=64, K-tile=64, 32 k-tiles.
// qkv layout: [B*T, 3072]; q at col h*64, k at 1024+h*64, v at 2048+h*64.
// out layout: [B*T, 1024] at col h*64.
// ---------------------------------------------------------------------------
#define FA_PAD 68
#define FA_SMEM ((64 * 64 + 64 * FA_PAD + 64 * FA_PAD + 64 * 64) * 4)

__global__ __launch_bounds__(256, 2)
void flash_attn_k(const float* __restrict__ qkv, float* __restrict__ out) {
    extern __shared__ float sm[];
    float* Qs  = sm;                            // [64][64]
    float* Ks  = sm + 64 * 64;                  // [64][68]
    float* Vst = sm + 64 * 64 + 64 * FA_PAD;    // [64 dcol][68 seq] (transposed)
    float* Ps  = sm + 64 * 64 + 2 * 64 * FA_PAD;// [64][64]

    const int qt = blockIdx.x;
    const int h  = blockIdx.y;
    const int b  = blockIdx.z;
    const int tid = threadIdx.x;
    const int tx = tid & 15;
    const int ty = tid >> 4;
    const int t0 = qt * 64;

    // Load Q tile, scaled by 1/sqrt(64)=0.125
    const float* qbase = qkv + ((size_t)(b * 2048 + t0)) * 3072 + h * 64;
#pragma unroll
    for (int it = 0; it < 4; it++) {
        const int row = ty + it * 16;
        const int col = tx * 4;
        float4 v = *(const float4*)(qbase + (size_t)row * 3072 + col);
        v.x *= 0.125f; v.y *= 0.125f; v.z *= 0.125f; v.w *= 0.125f;
        *(float4*)&Qs[row * 64 + col] = v;
    }

    float m[4], l[4], o[4][4];
#pragma unroll
    for (int i = 0; i < 4; i++) {
        m[i] = -INFINITY; l[i] = 0.f;
#pragma unroll
        for (int j = 0; j < 4; j++) o[i][j] = 0.f;
    }

    for (int kt = 0; kt < 32; kt++) {
        __syncthreads();  // protect Ks/Vst/Ps from previous iteration's readers

        const float* kbase = qkv + ((size_t)(b * 2048 + kt * 64)) * 3072 + 1024 + h * 64;
        const float* vbase = kbase + 1024;
#pragma unroll
        for (int it = 0; it < 4; it++) {
            const int row = ty + it * 16;
            const int col = tx * 4;
            const float4 kv = *(const float4*)(kbase + (size_t)row * 3072 + col);
            *(float4*)&Ks[row * FA_PAD + col] = kv;
            const float4 vv = *(const float4*)(vbase + (size_t)row * 3072 + col);
            Vst[(col + 0) * FA_PAD + row] = vv.x;
            Vst[(col + 1) * FA_PAD + row] = vv.y;
            Vst[(col + 2) * FA_PAD + row] = vv.z;
            Vst[(col + 3) * FA_PAD + row] = vv.w;
        }
        __syncthreads();

        // S = Q @ K^T (rows r=ty+16i, cols c=tx+16j)
        float s[4][4];
#pragma unroll
        for (int i = 0; i < 4; i++)
#pragma unroll
            for (int j = 0; j < 4; j++) s[i][j] = 0.f;

#pragma unroll 4
        for (int d4 = 0; d4 < 16; d4++) {
            float4 a[4], bb[4];
#pragma unroll
            for (int i = 0; i < 4; i++)
                a[i] = *(const float4*)&Qs[(ty + 16 * i) * 64 + d4 * 4];
#pragma unroll
            for (int j = 0; j < 4; j++)
                bb[j] = *(const float4*)&Ks[(tx + 16 * j) * FA_PAD + d4 * 4];
#pragma unroll
            for (int i = 0; i < 4; i++)
#pragma unroll
                for (int j = 0; j < 4; j++)
                    s[i][j] += a[i].x * bb[j].x + a[i].y * bb[j].y +
                               a[i].z * bb[j].z + a[i].w * bb[j].w;
        }

        // Online softmax (row reduce across tx = 16 lanes within warp)
#pragma unroll
        for (int i = 0; i < 4; i++) {
            float rmax = fmaxf(fmaxf(s[i][0], s[i][1]), fmaxf(s[i][2], s[i][3]));
#pragma unroll
            for (int off = 8; off >= 1; off >>= 1)
                rmax = fmaxf(rmax, __shfl_xor_sync(0xffffffffu, rmax, off));
            const float mnew  = fmaxf(m[i], rmax);
            const float alpha = __expf(m[i] - mnew);
            float rsum = 0.f;
#pragma unroll
            for (int j = 0; j < 4; j++) {
                s[i][j] = __expf(s[i][j] - mnew);
                rsum += s[i][j];
            }
#pragma unroll
            for (int off = 8; off >= 1; off >>= 1)
                rsum += __shfl_xor_sync(0xffffffffu, rsum, off);
            l[i] = l[i] * alpha + rsum;
            m[i] = mnew;
#pragma unroll
            for (int j = 0; j < 4; j++) o[i][j] *= alpha;
#pragma unroll
            for (int j = 0; j < 4; j++)
                Ps[(ty + 16 * i) * 64 + tx + 16 * j] = s[i][j];
        }
        __syncthreads();

        // O += P @ V   (o cols are dcol = tx+16j over DH=64)
#pragma unroll 4
        for (int c4 = 0; c4 < 16; c4++) {
            float4 p[4], v[4];
#pragma unroll
            for (int i = 0; i < 4; i++)
                p[i] = *(const float4*)&Ps[(ty + 16 * i) * 64 + c4 * 4];
#pragma unroll
            for (int j = 0; j < 4; j++)
                v[j] = *(const float4*)&Vst[(tx + 16 * j) * FA_PAD + c4 * 4];
#pragma unroll
            for (int i = 0; i < 4; i++)
#pragma unroll
                for (int j = 0; j < 4; j++)
                    o[i][j] += p[i].x * v[j].x + p[i].y * v[j].y +
                               p[i].z * v[j].z + p[i].w * v[j].w;
        }
    }

    // Write O / l  -> out[b, t0+r, h*64 + dcol]
#pragma unroll
    for (int i = 0; i < 4; i++) {
        const float invl = 1.0f / l[i];
        const size_t rbase = ((size_t)(b * 2048 + t0 + ty + 16 * i)) * 1024 + h * 64;
#pragma unroll
        for (int j = 0; j < 4; j++)
            out[rbase + tx + 16 * j] = o[i][j] * invl;
    }
}

// ---------------------------------------------------------------------------
// kernel_launch
// Input order (metadata): inputs, cond, attention_mask, ln1_g, ln1_b,
//   ln2_g, ln2_b, w_qkv, w_out, b_out, w1, b1, w2, b2
// ---------------------------------------------------------------------------
extern "C" void kernel_launch(void* const* d_in, const int* in_sizes, int n_in,
                              void* d_out, int out_size) {
    const float* inputs = (const float*)d_in[0];
    const float* ln1_g  = (const float*)d_in[3];
    const float* ln1_b  = (const float*)d_in[4];
    const float* ln2_g  = (const float*)d_in[5];
    const float* ln2_b  = (const float*)d_in[6];
    const float* w_qkv  = (const float*)d_in[7];
    const float* w_out  = (const float*)d_in[8];
    const float* b_out  = (const float*)d_in[9];
    const float* w1     = (const float*)d_in[10];
    const float* b1     = (const float*)d_in[11];
    const float* w2     = (const float*)d_in[12];
    const float* b2     = (const float*)d_in[13];
    float* out = (float*)d_out;

    float *xn, *qkv, *att, *x, *hn, *h;
    cudaGetSymbolAddress((void**)&xn,  g_xn);
    cudaGetSymbolAddress((void**)&qkv, g_qkv);
    cudaGetSymbolAddress((void**)&att, g_att);
    cudaGetSymbolAddress((void**)&x,   g_x);
    cudaGetSymbolAddress((void**)&hn,  g_hn);
    cudaGetSymbolAddress((void**)&h,   g_h);

    // 1. x_n = LN1(inputs)
    ln_k<<<M_ROWS, 256>>>(inputs, ln1_g, ln1_b, xn);

    // 2. qkv = x_n @ w_qkv    [4096,1024]x[1024,3072]
    sgemm_k<0><<<dim3(D3 / BN, M_ROWS / BM), 256>>>(
        xn, w_qkv, nullptr, nullptr, qkv, M_ROWS, D3, D_DIM);

    // 3. attention -> att [4096,1024]
    cudaFuncSetAttribute(flash_attn_k,
                         cudaFuncAttributeMaxDynamicSharedMemorySize, FA_SMEM);
    flash_attn_k<<<dim3(32, 16, 2), 256, FA_SMEM>>>(qkv, att);

    // 4. x = att @ w_out + b_out + inputs
    sgemm_k<2><<<dim3(D_DIM / BN, M_ROWS / BM), 256>>>(
        att, w_out, b_out, inputs, x, M_ROWS, D_DIM, D_DIM);

    // 5. h_n = LN2(x)
    ln_k<<<M_ROWS, 256>>>(x, ln2_g, ln2_b, hn);

    // 6. h = gelu(h_n @ w1 + b1)   [4096,1024]x[1024,4096]
    sgemm_k<3><<<dim3(MLP_D / BN, M_ROWS / BM), 256>>>(
        hn, w1, b1, nullptr, h, M_ROWS, MLP_D, D_DIM);

    // 7. out = h @ w2 + b2 + x     [4096,4096]x[4096,1024]
    sgemm_k<2><<<dim3(D_DIM / BN, M_ROWS / BM), 256>>>(
        h, w2, b2, x, out, M_ROWS, D_DIM, MLP_D);
}

// round 6
// speedup vs baseline: 1.4285x; 1.4285x over previous
#include <cuda_runtime.h>
#include <math.h>
#include <stdint.h>
#include <mma.h>

using namespace nvcuda;

// ---------------------------------------------------------------------------
// Problem constants: B=2, T=2048, D=1024, NH=16, DH=64, MLP=4096. M = 4096.
// ---------------------------------------------------------------------------
#define M_ROWS 4096
#define D_DIM  1024
#define D3     3072
#define MLP_D  4096

// Scratch (device globals; no allocation allowed)
__device__ float g_xn  [M_ROWS * D_DIM];
__device__ float g_qkv [M_ROWS * D3];
__device__ float g_att [M_ROWS * D_DIM];
__device__ float g_x   [M_ROWS * D_DIM];
__device__ float g_hn  [M_ROWS * D_DIM];
__device__ float g_h   [M_ROWS * MLP_D];

__device__ __forceinline__ float to_tf32(float x) {
    float y;
    asm("cvt.rna.tf32.f32 %0, %1;" : "=f"(y) : "f"(x));
    return y;
}

// ---------------------------------------------------------------------------
// LayerNorm: one block (256 threads) per row of 1024 floats.
// ---------------------------------------------------------------------------
__global__ void ln_k(const float* __restrict__ x, const float* __restrict__ g,
                     const float* __restrict__ b, float* __restrict__ y) {
    __shared__ float rs[8], rss[8], sh[2];
    const int row = blockIdx.x;
    const int tid = threadIdx.x;
    const float4 v = *(const float4*)(x + (size_t)row * 1024 + tid * 4);
    float s  = v.x + v.y + v.z + v.w;
    float ss = v.x * v.x + v.y * v.y + v.z * v.z + v.w * v.w;
#pragma unroll
    for (int off = 16; off >= 1; off >>= 1) {
        s  += __shfl_xor_sync(0xffffffffu, s, off);
        ss += __shfl_xor_sync(0xffffffffu, ss, off);
    }
    if ((tid & 31) == 0) { rs[tid >> 5] = s; rss[tid >> 5] = ss; }
    __syncthreads();
    if (tid == 0) {
        float S = 0.f, SS = 0.f;
#pragma unroll
        for (int w = 0; w < 8; w++) { S += rs[w]; SS += rss[w]; }
        sh[0] = S * (1.0f / 1024.0f);
        sh[1] = SS * (1.0f / 1024.0f);
    }
    __syncthreads();
    const float mu   = sh[0];
    const float var  = sh[1] - mu * mu;
    const float rstd = rsqrtf(var + 1e-5f);
    const float4 gg = *(const float4*)(g + tid * 4);
    const float4 bb = *(const float4*)(b + tid * 4);
    float4 o;
    o.x = (v.x - mu) * rstd * gg.x + bb.x;
    o.y = (v.y - mu) * rstd * gg.y + bb.y;
    o.z = (v.z - mu) * rstd * gg.z + bb.z;
    o.w = (v.w - mu) * rstd * gg.w + bb.w;
    *(float4*)(y + (size_t)row * 1024 + tid * 4) = o;
}

// ---------------------------------------------------------------------------
// WMMA tf32 GEMM: C[M,N] = A[M,K] @ B[K,N] (+ epilogue)
//   EPI 0: none   2: +bias[n]+res[m,n]   3: gelu(.+bias[n])
// CTA tile 128x128, BK=32, 256 threads (8 warps), warp tile 32x64.
// Smem: As[128][36] + Bs[32][132]; epilogue reuses smem as 8 x [32][68].
// ---------------------------------------------------------------------------
#define G_AS_LD 36
#define G_BS_LD 132
#define G_EP_LD 68
#define G_SMEM_FLOATS (8 * 32 * G_EP_LD)            // 17408 floats (> As+Bs = 8832)
#define G_SMEM (G_SMEM_FLOATS * 4)                  // 69632 bytes

template <int EPI>
__global__ __launch_bounds__(256, 2)
void gemm_wmma(const float* __restrict__ A, const float* __restrict__ B,
               const float* __restrict__ bias, const float* __restrict__ res,
               float* __restrict__ C, int M, int N, int K) {
    extern __shared__ float sm[];
    float* As = sm;                     // [128][36]
    float* Bs = sm + 128 * G_AS_LD;     // [32][132]

    const int tid  = threadIdx.x;
    const int wid  = tid >> 5;
    const int lane = tid & 31;
    const int m0 = blockIdx.y * 128;
    const int n0 = blockIdx.x * 128;
    const int wm = (wid & 3) * 32;      // warp row offset in tile
    const int wn = (wid >> 2) * 64;     // warp col offset in tile

    wmma::fragment<wmma::accumulator, 16, 16, 8, float> acc[2][4];
#pragma unroll
    for (int i = 0; i < 2; i++)
#pragma unroll
        for (int j = 0; j < 4; j++)
            wmma::fill_fragment(acc[i][j], 0.0f);

    for (int k0 = 0; k0 < K; k0 += 32) {
        // Load A tile: 128 rows x 32 k-floats (tf32-rounded)
#pragma unroll
        for (int v = 0; v < 4; v++) {
            const int id = v * 256 + tid;
            const int r  = id >> 3;
            const int c4 = (id & 7) * 4;
            float4 x = *(const float4*)(A + (size_t)(m0 + r) * K + k0 + c4);
            x.x = to_tf32(x.x); x.y = to_tf32(x.y); x.z = to_tf32(x.z); x.w = to_tf32(x.w);
            *(float4*)&As[r * G_AS_LD + c4] = x;
        }
        // Load B tile: 32 k-rows x 128 n-floats (natural [K,N] layout)
#pragma unroll
        for (int v = 0; v < 4; v++) {
            const int id = v * 256 + tid;
            const int r  = id >> 5;
            const int c4 = (id & 31) * 4;
            float4 x = *(const float4*)(B + (size_t)(k0 + r) * N + n0 + c4);
            x.x = to_tf32(x.x); x.y = to_tf32(x.y); x.z = to_tf32(x.z); x.w = to_tf32(x.w);
            *(float4*)&Bs[r * G_BS_LD + c4] = x;
        }
        __syncthreads();

#pragma unroll
        for (int kk = 0; kk < 4; kk++) {
            wmma::fragment<wmma::matrix_a, 16, 16, 8, wmma::precision::tf32,
                           wmma::row_major> af[2];
            wmma::fragment<wmma::matrix_b, 16, 16, 8, wmma::precision::tf32,
                           wmma::row_major> bf[4];
#pragma unroll
            for (int i = 0; i < 2; i++)
                wmma::load_matrix_sync(af[i], &As[(wm + i * 16) * G_AS_LD + kk * 8],
                                       G_AS_LD);
#pragma unroll
            for (int j = 0; j < 4; j++)
                wmma::load_matrix_sync(bf[j], &Bs[(kk * 8) * G_BS_LD + wn + j * 16],
                                       G_BS_LD);
#pragma unroll
            for (int i = 0; i < 2; i++)
#pragma unroll
                for (int j = 0; j < 4; j++)
                    wmma::mma_sync(acc[i][j], af[i], bf[j], acc[i][j]);
        }
        __syncthreads();
    }

    // Epilogue: each warp dumps its 32x64 patch to its own smem region,
    // then applies bias/residual/gelu and writes coalesced.
    float* ep = sm + wid * (32 * G_EP_LD);
#pragma unroll
    for (int i = 0; i < 2; i++)
#pragma unroll
        for (int j = 0; j < 4; j++)
            wmma::store_matrix_sync(&ep[(i * 16) * G_EP_LD + j * 16], acc[i][j],
                                    G_EP_LD, wmma::mem_row_major);
    __syncwarp();

#pragma unroll 4
    for (int r = 0; r < 32; r++) {
        const int m = m0 + wm + r;
#pragma unroll
        for (int cc = 0; cc < 2; cc++) {
            const int c = lane + cc * 32;
            const int n = n0 + wn + c;
            float v = ep[r * G_EP_LD + c];
            if (EPI >= 1) v += bias[n];
            if (EPI == 2) v += res[(size_t)m * N + n];
            if (EPI == 3) v = 0.5f * v * (1.0f + erff(v * 0.7071067811865476f));
            C[(size_t)m * N + n] = v;
        }
    }
}

// ---------------------------------------------------------------------------
// Flash attention (fp32, no mask): block = (qtile=64 rows, head h, batch b).
// ---------------------------------------------------------------------------
#define FA_PAD 68
#define FA_SMEM ((64 * 64 + 64 * FA_PAD + 64 * FA_PAD + 64 * 64) * 4)

__global__ __launch_bounds__(256, 2)
void flash_attn_k(const float* __restrict__ qkv, float* __restrict__ out) {
    extern __shared__ float sm[];
    float* Qs  = sm;
    float* Ks  = sm + 64 * 64;
    float* Vst = sm + 64 * 64 + 64 * FA_PAD;
    float* Ps  = sm + 64 * 64 + 2 * 64 * FA_PAD;

    const int qt = blockIdx.x;
    const int h  = blockIdx.y;
    const int b  = blockIdx.z;
    const int tid = threadIdx.x;
    const int tx = tid & 15;
    const int ty = tid >> 4;
    const int t0 = qt * 64;

    const float* qbase = qkv + ((size_t)(b * 2048 + t0)) * 3072 + h * 64;
#pragma unroll
    for (int it = 0; it < 4; it++) {
        const int row = ty + it * 16;
        const int col = tx * 4;
        float4 v = *(const float4*)(qbase + (size_t)row * 3072 + col);
        v.x *= 0.125f; v.y *= 0.125f; v.z *= 0.125f; v.w *= 0.125f;
        *(float4*)&Qs[row * 64 + col] = v;
    }

    float m[4], l[4], o[4][4];
#pragma unroll
    for (int i = 0; i < 4; i++) {
        m[i] = -INFINITY; l[i] = 0.f;
#pragma unroll
        for (int j = 0; j < 4; j++) o[i][j] = 0.f;
    }

    for (int kt = 0; kt < 32; kt++) {
        __syncthreads();
        const float* kbase = qkv + ((size_t)(b * 2048 + kt * 64)) * 3072 + 1024 + h * 64;
        const float* vbase = kbase + 1024;
#pragma unroll
        for (int it = 0; it < 4; it++) {
            const int row = ty + it * 16;
            const int col = tx * 4;
            const float4 kv = *(const float4*)(kbase + (size_t)row * 3072 + col);
            *(float4*)&Ks[row * FA_PAD + col] = kv;
            const float4 vv = *(const float4*)(vbase + (size_t)row * 3072 + col);
            Vst[(col + 0) * FA_PAD + row] = vv.x;
            Vst[(col + 1) * FA_PAD + row] = vv.y;
            Vst[(col + 2) * FA_PAD + row] = vv.z;
            Vst[(col + 3) * FA_PAD + row] = vv.w;
        }
        __syncthreads();

        float s[4][4];
#pragma unroll
        for (int i = 0; i < 4; i++)
#pragma unroll
            for (int j = 0; j < 4; j++) s[i][j] = 0.f;

#pragma unroll 4
        for (int d4 = 0; d4 < 16; d4++) {
            float4 a[4], bb[4];
#pragma unroll
            for (int i = 0; i < 4; i++)
                a[i] = *(const float4*)&Qs[(ty + 16 * i) * 64 + d4 * 4];
#pragma unroll
            for (int j = 0; j < 4; j++)
                bb[j] = *(const float4*)&Ks[(tx + 16 * j) * FA_PAD + d4 * 4];
#pragma unroll
            for (int i = 0; i < 4; i++)
#pragma unroll
                for (int j = 0; j < 4; j++)
                    s[i][j] += a[i].x * bb[j].x + a[i].y * bb[j].y +
                               a[i].z * bb[j].z + a[i].w * bb[j].w;
        }

#pragma unroll
        for (int i = 0; i < 4; i++) {
            float rmax = fmaxf(fmaxf(s[i][0], s[i][1]), fmaxf(s[i][2], s[i][3]));
#pragma unroll
            for (int off = 8; off >= 1; off >>= 1)
                rmax = fmaxf(rmax, __shfl_xor_sync(0xffffffffu, rmax, off));
            const float mnew  = fmaxf(m[i], rmax);
            const float alpha = __expf(m[i] - mnew);
            float rsum = 0.f;
#pragma unroll
            for (int j = 0; j < 4; j++) {
                s[i][j] = __expf(s[i][j] - mnew);
                rsum += s[i][j];
            }
#pragma unroll
            for (int off = 8; off >= 1; off >>= 1)
                rsum += __shfl_xor_sync(0xffffffffu, rsum, off);
            l[i] = l[i] * alpha + rsum;
            m[i] = mnew;
#pragma unroll
            for (int j = 0; j < 4; j++) o[i][j] *= alpha;
#pragma unroll
            for (int j = 0; j < 4; j++)
                Ps[(ty + 16 * i) * 64 + tx + 16 * j] = s[i][j];
        }
        __syncthreads();

#pragma unroll 4
        for (int c4 = 0; c4 < 16; c4++) {
            float4 p[4], v[4];
#pragma unroll
            for (int i = 0; i < 4; i++)
                p[i] = *(const float4*)&Ps[(ty + 16 * i) * 64 + c4 * 4];
#pragma unroll
            for (int j = 0; j < 4; j++)
                v[j] = *(const float4*)&Vst[(tx + 16 * j) * FA_PAD + c4 * 4];
#pragma unroll
            for (int i = 0; i < 4; i++)
#pragma unroll
                for (int j = 0; j < 4; j++)
                    o[i][j] += p[i].x * v[j].x + p[i].y * v[j].y +
                               p[i].z * v[j].z + p[i].w * v[j].w;
        }
    }

#pragma unroll
    for (int i = 0; i < 4; i++) {
        const float invl = 1.0f / l[i];
        const size_t rbase = ((size_t)(b * 2048 + t0 + ty + 16 * i)) * 1024 + h * 64;
#pragma unroll
        for (int j = 0; j < 4; j++)
            out[rbase + tx + 16 * j] = o[i][j] * invl;
    }
}

// ---------------------------------------------------------------------------
// kernel_launch
// ---------------------------------------------------------------------------
extern "C" void kernel_launch(void* const* d_in, const int* in_sizes, int n_in,
                              void* d_out, int out_size) {
    const float* inputs = (const float*)d_in[0];
    const float* ln1_g  = (const float*)d_in[3];
    const float* ln1_b  = (const float*)d_in[4];
    const float* ln2_g  = (const float*)d_in[5];
    const float* ln2_b  = (const float*)d_in[6];
    const float* w_qkv  = (const float*)d_in[7];
    const float* w_out  = (const float*)d_in[8];
    const float* b_out  = (const float*)d_in[9];
    const float* w1     = (const float*)d_in[10];
    const float* b1     = (const float*)d_in[11];
    const float* w2     = (const float*)d_in[12];
    const float* b2     = (const float*)d_in[13];
    float* out = (float*)d_out;

    float *xn, *qkv, *att, *x, *hn, *h;
    cudaGetSymbolAddress((void**)&xn,  g_xn);
    cudaGetSymbolAddress((void**)&qkv, g_qkv);
    cudaGetSymbolAddress((void**)&att, g_att);
    cudaGetSymbolAddress((void**)&x,   g_x);
    cudaGetSymbolAddress((void**)&hn,  g_hn);
    cudaGetSymbolAddress((void**)&h,   g_h);

    cudaFuncSetAttribute(gemm_wmma<0>, cudaFuncAttributeMaxDynamicSharedMemorySize, G_SMEM);
    cudaFuncSetAttribute(gemm_wmma<2>, cudaFuncAttributeMaxDynamicSharedMemorySize, G_SMEM);
    cudaFuncSetAttribute(gemm_wmma<3>, cudaFuncAttributeMaxDynamicSharedMemorySize, G_SMEM);
    cudaFuncSetAttribute(flash_attn_k, cudaFuncAttributeMaxDynamicSharedMemorySize, FA_SMEM);

    // 1. x_n = LN1(inputs)
    ln_k<<<M_ROWS, 256>>>(inputs, ln1_g, ln1_b, xn);

    // 2. qkv = x_n @ w_qkv   [4096,1024]x[1024,3072]
    gemm_wmma<0><<<dim3(D3 / 128, M_ROWS / 128), 256, G_SMEM>>>(
        xn, w_qkv, nullptr, nullptr, qkv, M_ROWS, D3, D_DIM);

    // 3. attention -> att
    flash_attn_k<<<dim3(32, 16, 2), 256, FA_SMEM>>>(qkv, att);

    // 4. x = att @ w_out + b_out + inputs
    gemm_wmma<2><<<dim3(D_DIM / 128, M_ROWS / 128), 256, G_SMEM>>>(
        att, w_out, b_out, inputs, x, M_ROWS, D_DIM, D_DIM);

    // 5. h_n = LN2(x)
    ln_k<<<M_ROWS, 256>>>(x, ln2_g, ln2_b, hn);

    // 6. h = gelu(h_n @ w1 + b1)
    gemm_wmma<3><<<dim3(MLP_D / 128, M_ROWS / 128), 256, G_SMEM>>>(
        hn, w1, b1, nullptr, h, M_ROWS, MLP_D, D_DIM);

    // 7. out = h @ w2 + b2 + x
    gemm_wmma<2><<<dim3(D_DIM / 128, M_ROWS / 128), 256, G_SMEM>>>(
        h, w2, b2, x, out, M_ROWS, D_DIM, MLP_D);
}

// round 8
// speedup vs baseline: 1.5985x; 1.1190x over previous
#include <cuda_runtime.h>
#include <math.h>
#include <stdint.h>
#include <mma.h>

using namespace nvcuda;

// ---------------------------------------------------------------------------
// Problem constants: B=2, T=2048, D=1024, NH=16, DH=64, MLP=4096. M = 4096.
// ---------------------------------------------------------------------------
#define M_ROWS 4096
#define D_DIM  1024
#define D3     3072
#define MLP_D  4096

// Scratch (device globals; no allocation allowed)
__device__ float g_xn  [M_ROWS * D_DIM];
__device__ float g_qkv [M_ROWS * D3];
__device__ float g_att [M_ROWS * D_DIM];
__device__ float g_x   [M_ROWS * D_DIM];
__device__ float g_hn  [M_ROWS * D_DIM];
__device__ float g_h   [M_ROWS * MLP_D];
// tf32-pre-rounded weights
__device__ float g_wqkv_r[D_DIM * D3];
__device__ float g_wout_r[D_DIM * D_DIM];
__device__ float g_w1_r  [D_DIM * MLP_D];
__device__ float g_w2_r  [MLP_D * D_DIM];

__device__ __forceinline__ float to_tf32(float x) {
    float y;
    asm("cvt.rna.tf32.f32 %0, %1;" : "=f"(y) : "f"(x));
    return y;
}

// cp.async helpers
__device__ __forceinline__ void cp16(uint32_t dst, const void* src) {
    asm volatile("cp.async.cg.shared.global [%0], [%1], 16;" :: "r"(dst), "l"(src));
}
#define CP_COMMIT() asm volatile("cp.async.commit_group;" ::: "memory")
template <int N>
__device__ __forceinline__ void cp_wait() {
    asm volatile("cp.async.wait_group %0;" :: "n"(N) : "memory");
}

// ---------------------------------------------------------------------------
// Elementwise tf32 rounding (for weights). n % 1024 == 0.
// ---------------------------------------------------------------------------
__global__ void round_tf32_k(const float* __restrict__ in, float* __restrict__ out) {
    const int i = (blockIdx.x * 256 + threadIdx.x) * 4;
    float4 v = *(const float4*)(in + i);
    v.x = to_tf32(v.x); v.y = to_tf32(v.y); v.z = to_tf32(v.z); v.w = to_tf32(v.w);
    *(float4*)(out + i) = v;
}

// ---------------------------------------------------------------------------
// LayerNorm: one block (256 threads) per row of 1024 floats.
// ROUND: round output to tf32 (when output feeds only a GEMM A-operand).
// ---------------------------------------------------------------------------
template <int ROUND>
__global__ void ln_k(const float* __restrict__ x, const float* __restrict__ g,
                     const float* __restrict__ b, float* __restrict__ y) {
    __shared__ float rs[8], rss[8], sh[2];
    const int row = blockIdx.x;
    const int tid = threadIdx.x;
    const float4 v = *(const float4*)(x + (size_t)row * 1024 + tid * 4);
    float s  = v.x + v.y + v.z + v.w;
    float ss = v.x * v.x + v.y * v.y + v.z * v.z + v.w * v.w;
#pragma unroll
    for (int off = 16; off >= 1; off >>= 1) {
        s  += __shfl_xor_sync(0xffffffffu, s, off);
        ss += __shfl_xor_sync(0xffffffffu, ss, off);
    }
    if ((tid & 31) == 0) { rs[tid >> 5] = s; rss[tid >> 5] = ss; }
    __syncthreads();
    if (tid == 0) {
        float S = 0.f, SS = 0.f;
#pragma unroll
        for (int w = 0; w < 8; w++) { S += rs[w]; SS += rss[w]; }
        sh[0] = S * (1.0f / 1024.0f);
        sh[1] = SS * (1.0f / 1024.0f);
    }
    __syncthreads();
    const float mu   = sh[0];
    const float var  = sh[1] - mu * mu;
    const float rstd = rsqrtf(var + 1e-5f);
    const float4 gg = *(const float4*)(g + tid * 4);
    const float4 bb = *(const float4*)(b + tid * 4);
    float4 o;
    o.x = (v.x - mu) * rstd * gg.x + bb.x;
    o.y = (v.y - mu) * rstd * gg.y + bb.y;
    o.z = (v.z - mu) * rstd * gg.z + bb.z;
    o.w = (v.w - mu) * rstd * gg.w + bb.w;
    if (ROUND) {
        o.x = to_tf32(o.x); o.y = to_tf32(o.y); o.z = to_tf32(o.z); o.w = to_tf32(o.w);
    }
    *(float4*)(y + (size_t)row * 1024 + tid * 4) = o;
}

// ---------------------------------------------------------------------------
// WMMA tf32 GEMM with cp.async 2-stage pipeline.
// C[M,N] = A[M,K] @ B[K,N] (+ epilogue). A, B must be tf32-pre-rounded.
//   EPI 0: none   2: +bias+res   3: round_tf32(gelu(.+bias))
// CTA tile 128x128, BK=32, 256 threads, 8 warps, warp tile 32x64.
// ---------------------------------------------------------------------------
#define G_AS_LD 36
#define G_BS_LD 132
#define G_STG_FLOATS (128 * G_AS_LD + 32 * G_BS_LD)   // 8832
#define G_EP_LD 68
#define G_SMEM_FLOATS (2 * G_STG_FLOATS)              // 17664 > 8*32*68=17408 (epi)
#define G_SMEM (G_SMEM_FLOATS * 4)                    // 70656 bytes

__device__ __forceinline__ void g_load_stage(
    const float* __restrict__ A, const float* __restrict__ B,
    int N, int K, int m0, int n0, int k0, float* As, float* Bs, int tid) {
#pragma unroll
    for (int v = 0; v < 4; v++) {
        const int id = v * 256 + tid;
        const int r  = id >> 3;
        const int c4 = (id & 7) * 4;
        cp16((uint32_t)__cvta_generic_to_shared(&As[r * G_AS_LD + c4]),
             A + (size_t)(m0 + r) * K + k0 + c4);
    }
#pragma unroll
    for (int v = 0; v < 4; v++) {
        const int id = v * 256 + tid;
        const int r  = id >> 5;
        const int c4 = (id & 31) * 4;
        cp16((uint32_t)__cvta_generic_to_shared(&Bs[r * G_BS_LD + c4]),
             B + (size_t)(k0 + r) * N + n0 + c4);
    }
}

template <int EPI>
__global__ __launch_bounds__(256, 2)
void gemm_wmma(const float* __restrict__ A, const float* __restrict__ B,
               const float* __restrict__ bias, const float* __restrict__ res,
               float* __restrict__ C, int M, int N, int K) {
    extern __shared__ float sm[];
    float* As[2] = {sm, sm + G_STG_FLOATS};
    float* Bs[2] = {sm + 128 * G_AS_LD, sm + G_STG_FLOATS + 128 * G_AS_LD};

    const int tid  = threadIdx.x;
    const int wid  = tid >> 5;
    const int lane = tid & 31;
    const int m0 = blockIdx.y * 128;
    const int n0 = blockIdx.x * 128;
    const int wm = (wid & 3) * 32;
    const int wn = (wid >> 2) * 64;

    wmma::fragment<wmma::accumulator, 16, 16, 8, float> acc[2][4];
#pragma unroll
    for (int i = 0; i < 2; i++)
#pragma unroll
        for (int j = 0; j < 4; j++)
            wmma::fill_fragment(acc[i][j], 0.0f);

    const int NK = K / 32;
    g_load_stage(A, B, N, K, m0, n0, 0, As[0], Bs[0], tid);
    CP_COMMIT();

    for (int kt = 0; kt < NK; kt++) {
        if (kt + 1 < NK) {
            g_load_stage(A, B, N, K, m0, n0, (kt + 1) * 32,
                         As[(kt + 1) & 1], Bs[(kt + 1) & 1], tid);
            CP_COMMIT();
            cp_wait<1>();
        } else {
            cp_wait<0>();
        }
        __syncthreads();

        const float* as = As[kt & 1];
        const float* bs = Bs[kt & 1];
#pragma unroll
        for (int kk = 0; kk < 4; kk++) {
            wmma::fragment<wmma::matrix_a, 16, 16, 8, wmma::precision::tf32,
                           wmma::row_major> af[2];
            wmma::fragment<wmma::matrix_b, 16, 16, 8, wmma::precision::tf32,
                           wmma::row_major> bf[4];
#pragma unroll
            for (int i = 0; i < 2; i++)
                wmma::load_matrix_sync(af[i], &as[(wm + i * 16) * G_AS_LD + kk * 8],
                                       G_AS_LD);
#pragma unroll
            for (int j = 0; j < 4; j++)
                wmma::load_matrix_sync(bf[j], &bs[(kk * 8) * G_BS_LD + wn + j * 16],
                                       G_BS_LD);
#pragma unroll
            for (int i = 0; i < 2; i++)
#pragma unroll
                for (int j = 0; j < 4; j++)
                    wmma::mma_sync(acc[i][j], af[i], bf[j], acc[i][j]);
        }
        __syncthreads();
    }

    // Epilogue: warp-private smem patch, then coalesced global write.
    float* ep = sm + wid * (32 * G_EP_LD);
#pragma unroll
    for (int i = 0; i < 2; i++)
#pragma unroll
        for (int j = 0; j < 4; j++)
            wmma::store_matrix_sync(&ep[(i * 16) * G_EP_LD + j * 16], acc[i][j],
                                    G_EP_LD, wmma::mem_row_major);
    __syncwarp();

#pragma unroll 4
    for (int r = 0; r < 32; r++) {
        const int m = m0 + wm + r;
#pragma unroll
        for (int cc = 0; cc < 2; cc++) {
            const int c = lane + cc * 32;
            const int n = n0 + wn + c;
            float v = ep[r * G_EP_LD + c];
            if (EPI >= 1) v += bias[n];
            if (EPI == 2) v += res[(size_t)m * N + n];
            if (EPI == 3) {
                v = 0.5f * v * (1.0f + erff(v * 0.7071067811865476f));
                v = to_tf32(v);
            }
            C[(size_t)m * N + n] = v;
        }
    }
}

// ---------------------------------------------------------------------------
// Tensor-core flash attention (tf32 WMMA, fp32 softmax/accum, no mask).
// Block: 256 threads (8 warps) handles 64 q-rows x one head x one batch.
// Warp w: rows r0=(w&3)*16, cols c0=(w>>2)*32 of each 64x64 tile.
// Smem tiles LD=72. Online softmax state in smem (m,l per row).
// ---------------------------------------------------------------------------
#define FT_LD 72
#define FT_T  (64 * FT_LD)
#define FT_SMEM ((5 * FT_T + 128) * 4)   // Qs,Ks,Vs,Ss,Os + m,l = 92672 B

__global__ __launch_bounds__(256, 2)
void flash_attn_tc(const float* __restrict__ qkv, float* __restrict__ out) {
    extern __shared__ float sm[];
    float* Qs = sm;
    float* Ks = sm + FT_T;
    float* Vs = sm + 2 * FT_T;
    float* Ss = sm + 3 * FT_T;
    float* Os = sm + 4 * FT_T;
    float* m_s = sm + 5 * FT_T;
    float* l_s = m_s + 64;

    const int qt = blockIdx.x;
    const int h  = blockIdx.y;
    const int b  = blockIdx.z;
    const int tid  = threadIdx.x;
    const int wid  = tid >> 5;
    const int r0 = (wid & 3) * 16;
    const int c0 = (wid >> 2) * 32;
    const int t0 = qt * 64;

    // Load Q (scaled by 1/8, tf32-rounded); zero Os; init m,l.
    const float* qbase = qkv + ((size_t)(b * 2048 + t0)) * 3072 + h * 64;
#pragma unroll
    for (int v = 0; v < 4; v++) {
        const int id = v * 256 + tid;
        const int r  = id >> 4;
        const int c4 = (id & 15) * 4;
        float4 x = *(const float4*)(qbase + (size_t)r * 3072 + c4);
        x.x = to_tf32(x.x * 0.125f); x.y = to_tf32(x.y * 0.125f);
        x.z = to_tf32(x.z * 0.125f); x.w = to_tf32(x.w * 0.125f);
        *(float4*)&Qs[r * FT_LD + c4] = x;
        *(float4*)&Os[r * FT_LD + c4] = make_float4(0.f, 0.f, 0.f, 0.f);
    }
    if (tid < 64) { m_s[tid] = -INFINITY; l_s[tid] = 0.f; }
    __syncthreads();

    for (int kt = 0; kt < 32; kt++) {
        // Load K, V tiles (tf32-rounded)
        const float* kbase = qkv + ((size_t)(b * 2048 + kt * 64)) * 3072 + 1024 + h * 64;
#pragma unroll
        for (int v = 0; v < 4; v++) {
            const int id = v * 256 + tid;
            const int r  = id >> 4;
            const int c4 = (id & 15) * 4;
            float4 x = *(const float4*)(kbase + (size_t)r * 3072 + c4);
            x.x = to_tf32(x.x); x.y = to_tf32(x.y); x.z = to_tf32(x.z); x.w = to_tf32(x.w);
            *(float4*)&Ks[r * FT_LD + c4] = x;
            float4 y = *(const float4*)(kbase + 1024 + (size_t)r * 3072 + c4);
            y.x = to_tf32(y.x); y.y = to_tf32(y.y); y.z = to_tf32(y.z); y.w = to_tf32(y.w);
            *(float4*)&Vs[r * FT_LD + c4] = y;
        }
        __syncthreads();

        // S = Q @ K^T  (warp patch 16x32 -> 2 frags)
        {
            wmma::fragment<wmma::accumulator, 16, 16, 8, float> sa[2];
            wmma::fill_fragment(sa[0], 0.f);
            wmma::fill_fragment(sa[1], 0.f);
#pragma unroll
            for (int kk = 0; kk < 8; kk++) {
                wmma::fragment<wmma::matrix_a, 16, 16, 8, wmma::precision::tf32,
                               wmma::row_major> af;
                wmma::fragment<wmma::matrix_b, 16, 16, 8, wmma::precision::tf32,
                               wmma::col_major> bf[2];
                wmma::load_matrix_sync(af, &Qs[r0 * FT_LD + kk * 8], FT_LD);
#pragma unroll
                for (int j = 0; j < 2; j++)
                    wmma::load_matrix_sync(bf[j], &Ks[(c0 + j * 16) * FT_LD + kk * 8],
                                           FT_LD);
#pragma unroll
                for (int j = 0; j < 2; j++)
                    wmma::mma_sync(sa[j], af, bf[j], sa[j]);
            }
#pragma unroll
            for (int j = 0; j < 2; j++)
                wmma::store_matrix_sync(&Ss[r0 * FT_LD + c0 + j * 16], sa[j],
                                        FT_LD, wmma::mem_row_major);
        }
        __syncthreads();

        // Online softmax: 4 threads per row, 16 cols each.
        {
            const int row = tid >> 2;
            const int qgrp = tid & 3;
            float* srow = &Ss[row * FT_LD + qgrp * 16];
            float rmax = -INFINITY;
#pragma unroll
            for (int c = 0; c < 16; c++) rmax = fmaxf(rmax, srow[c]);
            rmax = fmaxf(rmax, __shfl_xor_sync(0xffffffffu, rmax, 1));
            rmax = fmaxf(rmax, __shfl_xor_sync(0xffffffffu, rmax, 2));
            const float mold = m_s[row];
            const float mnew = fmaxf(mold, rmax);
            const float alpha = __expf(mold - mnew);
            float rsum = 0.f;
#pragma unroll
            for (int c = 0; c < 16; c++) {
                const float p = __expf(srow[c] - mnew);
                srow[c] = p;
                rsum += p;
            }
            rsum += __shfl_xor_sync(0xffffffffu, rsum, 1);
            rsum += __shfl_xor_sync(0xffffffffu, rsum, 2);
            if (qgrp == 0) { m_s[row] = mnew; l_s[row] = l_s[row] * alpha + rsum; }
            // rescale O row
            float* orow = &Os[row * FT_LD + qgrp * 16];
#pragma unroll
            for (int c = 0; c < 16; c++) orow[c] *= alpha;
        }
        __syncthreads();

        // O += P @ V  (acc loaded from / stored back to Os)
        {
            wmma::fragment<wmma::accumulator, 16, 16, 8, float> oa[2];
#pragma unroll
            for (int j = 0; j < 2; j++)
                wmma::load_matrix_sync(oa[j], &Os[r0 * FT_LD + c0 + j * 16],
                                       FT_LD, wmma::mem_row_major);
#pragma unroll
            for (int kk = 0; kk < 8; kk++) {
                wmma::fragment<wmma::matrix_a, 16, 16, 8, wmma::precision::tf32,
                               wmma::row_major> pf;
                wmma::fragment<wmma::matrix_b, 16, 16, 8, wmma::precision::tf32,
                               wmma::row_major> vf[2];
                wmma::load_matrix_sync(pf, &Ss[r0 * FT_LD + kk * 8], FT_LD);
#pragma unroll
                for (int j = 0; j < 2; j++)
                    wmma::load_matrix_sync(vf[j], &Vs[(kk * 8) * FT_LD + c0 + j * 16],
                                           FT_LD);
#pragma unroll
                for (int j = 0; j < 2; j++)
                    wmma::mma_sync(oa[j], pf, vf[j], oa[j]);
            }
#pragma unroll
            for (int j = 0; j < 2; j++)
                wmma::store_matrix_sync(&Os[r0 * FT_LD + c0 + j * 16], oa[j],
                                        FT_LD, wmma::mem_row_major);
        }
        __syncthreads();
    }

    // Write out: att[b, t0+row, h*64+c] = round(O/l). 4 threads/row, 16 cols.
    {
        const int row = tid >> 2;
        const int qgrp = tid & 3;
        const float invl = 1.0f / l_s[row];
        const size_t obase = ((size_t)(b * 2048 + t0 + row)) * 1024 + h * 64 + qgrp * 16;
        const float* orow = &Os[row * FT_LD + qgrp * 16];
#pragma unroll
        for (int c4 = 0; c4 < 4; c4++) {
            float4 v = *(const float4*)(orow + c4 * 4);
            v.x = to_tf32(v.x * invl); v.y = to_tf32(v.y * invl);
            v.z = to_tf32(v.z * invl); v.w = to_tf32(v.w * invl);
            *(float4*)(out + obase + c4 * 4) = v;
        }
    }
}

// ---------------------------------------------------------------------------
// kernel_launch
// ---------------------------------------------------------------------------
extern "C" void kernel_launch(void* const* d_in, const int* in_sizes, int n_in,
                              void* d_out, int out_size) {
    const float* inputs = (const float*)d_in[0];
    const float* ln1_g  = (const float*)d_in[3];
    const float* ln1_b  = (const float*)d_in[4];
    const float* ln2_g  = (const float*)d_in[5];
    const float* ln2_b  = (const float*)d_in[6];
    const float* w_qkv  = (const float*)d_in[7];
    const float* w_out  = (const float*)d_in[8];
    const float* b_out  = (const float*)d_in[9];
    const float* w1     = (const float*)d_in[10];
    const float* b1     = (const float*)d_in[11];
    const float* w2     = (const float*)d_in[12];
    const float* b2     = (const float*)d_in[13];
    float* out = (float*)d_out;

    float *xn, *qkv, *att, *x, *hn, *h, *wqkv_r, *wout_r, *w1_r, *w2_r;
    cudaGetSymbolAddress((void**)&xn,     g_xn);
    cudaGetSymbolAddress((void**)&qkv,    g_qkv);
    cudaGetSymbolAddress((void**)&att,    g_att);
    cudaGetSymbolAddress((void**)&x,      g_x);
    cudaGetSymbolAddress((void**)&hn,     g_hn);
    cudaGetSymbolAddress((void**)&h,      g_h);
    cudaGetSymbolAddress((void**)&wqkv_r, g_wqkv_r);
    cudaGetSymbolAddress((void**)&wout_r, g_wout_r);
    cudaGetSymbolAddress((void**)&w1_r,   g_w1_r);
    cudaGetSymbolAddress((void**)&w2_r,   g_w2_r);

    cudaFuncSetAttribute(gemm_wmma<0>, cudaFuncAttributeMaxDynamicSharedMemorySize, G_SMEM);
    cudaFuncSetAttribute(gemm_wmma<2>, cudaFuncAttributeMaxDynamicSharedMemorySize, G_SMEM);
    cudaFuncSetAttribute(gemm_wmma<3>, cudaFuncAttributeMaxDynamicSharedMemorySize, G_SMEM);
    cudaFuncSetAttribute(flash_attn_tc, cudaFuncAttributeMaxDynamicSharedMemorySize, FT_SMEM);

    // 0. Pre-round weights to tf32
    round_tf32_k<<<(D_DIM * D3)    / 1024, 256>>>(w_qkv, wqkv_r);
    round_tf32_k<<<(D_DIM * D_DIM) / 1024, 256>>>(w_out, wout_r);
    round_tf32_k<<<(D_DIM * MLP_D) / 1024, 256>>>(w1, w1_r);
    round_tf32_k<<<(MLP_D * D_DIM) / 1024, 256>>>(w2, w2_r);

    // 1. x_n = round(LN1(inputs))
    ln_k<1><<<M_ROWS, 256>>>(inputs, ln1_g, ln1_b, xn);

    // 2. qkv = x_n @ w_qkv
    gemm_wmma<0><<<dim3(D3 / 128, M_ROWS / 128), 256, G_SMEM>>>(
        xn, wqkv_r, nullptr, nullptr, qkv, M_ROWS, D3, D_DIM);

    // 3. attention -> att (tf32-rounded)
    flash_attn_tc<<<dim3(32, 16, 2), 256, FT_SMEM>>>(qkv, att);

    // 4. x = att @ w_out + b_out + inputs
    gemm_wmma<2><<<dim3(D_DIM / 128, M_ROWS / 128), 256, G_SMEM>>>(
        att, wout_r, b_out, inputs, x, M_ROWS, D_DIM, D_DIM);

    // 5. h_n = round(LN2(x))
    ln_k<1><<<M_ROWS, 256>>>(x, ln2_g, ln2_b, hn);

    // 6. h = round(gelu(h_n @ w1 + b1))
    gemm_wmma<3><<<dim3(MLP_D / 128, M_ROWS / 128), 256, G_SMEM>>>(
        hn, w1_r, b1, nullptr, h, M_ROWS, MLP_D, D_DIM);

    // 7. out = h @ w2 + b2 + x
    gemm_wmma<2><<<dim3(D_DIM / 128, M_ROWS / 128), 256, G_SMEM>>>(
        h, w2_r, b2, x, out, M_ROWS, D_DIM, MLP_D);
}